// round 14
// baseline (speedup 1.0000x reference)
#include <cuda_runtime.h>

// EfronLossPenalty — bucketized Efron Cox loss, times in [0, 8192).
// Only per-bucket (d, ers, rss) matter; block log-sum via falling factorial
// -> cancellation-free float Stirling difference.
//
// k_accum: byte-identical to R13 best (branch-free 32-bit RED, PDL trigger).
// k_post:  16 blocks x 128 threads, 4 buckets/thread (uint4 loads/zeroing),
//          ONE 16-participant barrier publishing float2{risk,d} chunks; nev
//          derived from chunks; contributions atomicAdd'ed straight into out
//          (block 0 zeroes out before its barrier arrive -> ordering safe).

#define NBINS 8192
#define NREP  16
#define BANK  (NREP * NBINS)
#define FIX_NE 65536.0f
#define FIX_EV 1024.0f
#define POST_BLOCKS 16
#define POST_THREADS 128
#define BPT 4   // buckets per thread: 16*128*4 = 8192

// Static scratch — zero at module load; every launch restores the all-zero
// invariant before exiting (graph-replay safe).
__device__ unsigned g_C[2 * BANK];
__device__ float2 g_chunk2[POST_BLOCKS];   // {risk_sum, d_sum} per block
__device__ float g_elr;
__device__ unsigned g_done1;
__device__ unsigned g_done2;

__device__ __forceinline__ float block_reduce_sum(float v) {
    __shared__ float s[32];
    int lane = threadIdx.x & 31;
    int wid  = threadIdx.x >> 5;
    #pragma unroll
    for (int o = 16; o > 0; o >>= 1) v += __shfl_down_sync(0xffffffffu, v, o);
    if (lane == 0) s[wid] = v;
    __syncthreads();
    int nw = (blockDim.x + 31) >> 5;
    v = (threadIdx.x < nw) ? s[threadIdx.x] : 0.0f;
    if (wid == 0) {
        #pragma unroll
        for (int o = 16; o > 0; o >>= 1) v += __shfl_down_sync(0xffffffffu, v, o);
    }
    __syncthreads();   // protect s[] against reuse
    return v;          // valid in thread 0
}

__device__ __forceinline__ void accum_one(int t, int e, float x, unsigned repbase, float& elr) {
    float w = __expf(x);
    float scale = e ? FIX_EV : FIX_NE;            // FSEL
    unsigned wi = (unsigned)fmaf(w, scale, 0.5f); // one FFMA + one F2I
    unsigned val = wi + ((unsigned)e << 24);      // count tag (0 for non-events)
    unsigned idx = repbase + (unsigned)t + (unsigned)e * (unsigned)BANK;
    atomicAdd(&g_C[idx], val);                    // no return use -> REDG.32
    elr += e ? x : 0.0f;
}

__global__ void __launch_bounds__(256) k_accum(
        const int* __restrict__ times, const int* __restrict__ events,
        const float* __restrict__ lr, int n) {
    int tid = blockIdx.x * blockDim.x + threadIdx.x;
    int stride = gridDim.x * blockDim.x;
    unsigned repbase = (((unsigned)(tid >> 5)) & (NREP - 1)) * NBINS;

    const int4*   t4 = (const int4*)times;
    const int4*   e4 = (const int4*)events;
    const float4* l4 = (const float4*)lr;
    int n4 = n >> 2;

    float elr = 0.0f;
    int i = tid;
    // 8 elements per iteration: two int4/float4 triplets in flight (deeper MLP)
    for (; i + stride < n4; i += 2 * stride) {
        int4   ta = t4[i],          tb = t4[i + stride];
        int4   ea = e4[i],          eb = e4[i + stride];
        float4 la = l4[i],          lb = l4[i + stride];
        accum_one(ta.x, ea.x, la.x, repbase, elr);
        accum_one(ta.y, ea.y, la.y, repbase, elr);
        accum_one(ta.z, ea.z, la.z, repbase, elr);
        accum_one(ta.w, ea.w, la.w, repbase, elr);
        accum_one(tb.x, eb.x, lb.x, repbase, elr);
        accum_one(tb.y, eb.y, lb.y, repbase, elr);
        accum_one(tb.z, eb.z, lb.z, repbase, elr);
        accum_one(tb.w, eb.w, lb.w, repbase, elr);
    }
    for (; i < n4; i += stride) {
        int4   tv = t4[i];
        int4   ev = e4[i];
        float4 lv = l4[i];
        accum_one(tv.x, ev.x, lv.x, repbase, elr);
        accum_one(tv.y, ev.y, lv.y, repbase, elr);
        accum_one(tv.z, ev.z, lv.z, repbase, elr);
        accum_one(tv.w, ev.w, lv.w, repbase, elr);
    }
    int base = n4 << 2;
    int rem  = n - base;
    if (tid < rem) accum_one(times[base + tid], events[base + tid], lr[base + tid], repbase, elr);

    float bsum = block_reduce_sum(elr);
    if (threadIdx.x == 0 && bsum != 0.0f) atomicAdd(&g_elr, bsum);

    // PDL: allow dependent k_post grid to launch while remaining blocks drain.
    cudaTriggerProgrammaticLaunchCompletion();
}

// Post-pass: vectorized replica reduce (+ re-zero), ONE cross-block barrier
// publishing {risk,d} chunks, per-bucket Efron terms, direct atomicAdd to out.
__global__ void __launch_bounds__(POST_THREADS) k_post(float* __restrict__ out, int out_n) {
    // out is untouched by k_accum: block 0 may zero it pre-sync (PDL preamble).
    // Ordering vs other blocks' atomicAdds is guaranteed by the barrier below
    // (block 0 arrives only after zeroing; contributions happen only after
    // ALL blocks passed the barrier).
    if (blockIdx.x == 0) {
        for (int j = threadIdx.x; j < out_n; j += POST_THREADS) out[j] = 0.0f;
    }

    // PDL: wait until ALL accum blocks completed (their writes visible).
    cudaGridDependencySynchronize();

    float elr = 0.0f;
    if (threadIdx.x == 0) elr = g_elr;   // read before any reset can occur

    // --- phase 1: reduce over replicas + banks (uint4), restore zeros ---
    unsigned b0 = (unsigned)(blockIdx.x * POST_THREADS + threadIdx.x) * BPT;
    unsigned nef[BPT] = {0u, 0u, 0u, 0u};
    unsigned cf [BPT] = {0u, 0u, 0u, 0u};
    unsigned ef [BPT] = {0u, 0u, 0u, 0u};
    const uint4 z4 = make_uint4(0u, 0u, 0u, 0u);
    #pragma unroll
    for (int r = 0; r < NREP; r++) {
        unsigned base = (unsigned)r * NBINS + b0;
        uint4 v0 = *(const uint4*)&g_C[base];
        uint4 v1 = *(const uint4*)&g_C[base + BANK];
        *(uint4*)&g_C[base]        = z4;
        *(uint4*)&g_C[base + BANK] = z4;
        nef[0] += v0.x; nef[1] += v0.y; nef[2] += v0.z; nef[3] += v0.w;
        cf[0] += v1.x >> 24; cf[1] += v1.y >> 24; cf[2] += v1.z >> 24; cf[3] += v1.w >> 24;
        ef[0] += v1.x & 0x00FFFFFFu; ef[1] += v1.y & 0x00FFFFFFu;
        ef[2] += v1.z & 0x00FFFFFFu; ef[3] += v1.w & 0x00FFFFFFu;
    }
    float risk[BPT], ers[BPT];
    int   d[BPT];
    float s_t = 0.0f;   // this thread's total risk
    int   d_t = 0;      // this thread's total events
    #pragma unroll
    for (int j = 0; j < BPT; j++) {
        d[j]    = (int)cf[j];
        ers[j]  = (float)ef[j] * (1.0f / FIX_EV);
        risk[j] = (float)nef[j] * (1.0f / FIX_NE) + ers[j];
        s_t += risk[j];
        d_t += d[j];
    }

    // --- phase 2: the ONE cross-block barrier ({risk,d} chunk publish) ---
    float crisk = block_reduce_sum(s_t);
    float cd    = block_reduce_sum((float)d_t);
    if (threadIdx.x == 0) {
        g_chunk2[blockIdx.x] = make_float2(crisk, cd);
        __threadfence();
        atomicAdd(&g_done1, 1u);
        while (*((volatile unsigned*)&g_done1) < gridDim.x) { }
    }
    __syncthreads();
    __threadfence();

    float suffix_base = 0.0f;   // risk in blocks above this one
    float nev = 0.0f;           // total events (all chunks)
    #pragma unroll
    for (int j = 0; j < POST_BLOCKS; j++) {
        float2 c = g_chunk2[j];
        if (j > blockIdx.x) suffix_base += c.x;
        nev += c.y;
    }
    float inv_nev = 1.0f / fmaxf(nev, 1.0f);

    // intra-block suffix over thread sums (inclusive: I[t] = sum_{t'>=t} s_t')
    __shared__ float sv[POST_THREADS];
    sv[threadIdx.x] = s_t;
    __syncthreads();
    for (int off = 1; off < POST_THREADS; off <<= 1) {
        float add = (threadIdx.x + off < POST_THREADS) ? sv[threadIdx.x + off] : 0.0f;
        __syncthreads();
        sv[threadIdx.x] += add;
        __syncthreads();
    }
    // sum of risk over buckets strictly above this thread's 4:
    float run = suffix_base + sv[threadIdx.x] - s_t;

    // --- phase 3: Efron terms for 4 buckets (descending index) ---
    float term = 0.0f;
    #pragma unroll
    for (int j = BPT - 1; j >= 0; j--) {
        run += risk[j];          // inclusive suffix at bucket b0+j
        float rss = run;
        int dj = d[j];
        if (dj == 1) {
            term += logf(rss + 1e-12f);
        } else if (dj > 1) {
            float s  = ers[j] / (float)dj;
            float x  = rss / s;
            float a  = x + 1.0f;
            float bb = x - (float)dj + 1.0f;
            if (bb > 0.5f) {
                // F(z) = (z-1/2)ln z - z + 1/(12z); F(a)-F(b) cancellation-free
                float la = logf(a), lb = logf(bb);
                float L  = 0.5f * (la + lb);
                float m  = 0.5f * (a + bb);
                float dlt = log1pf((float)dj / bb);
                term += (float)dj * (logf(s) + L - 1.0f)
                      + (m - 0.5f) * dlt
                      + (1.0f / 12.0f) * (1.0f / a - 1.0f / bb);
            } else {   // near-clamp fallback (matches reference per-term max)
                for (int l = 0; l < dj; l++)
                    term += __logf(fmaxf(rss - (float)l * s, 1e-12f));
            }
        }
    }

    // --- phase 4: direct contribution to out; no second barrier ---
    float tsum = block_reduce_sum(term);
    if (threadIdx.x == 0) {
        float contrib = tsum * inv_nev;
        if (blockIdx.x == 0) contrib -= elr * inv_nev;
        if (contrib != 0.0f) {
            for (int j = 0; j < out_n; j++) atomicAdd(&out[j], contrib);
        }
        // bookkeeping reset: last finisher restores the all-zero invariant.
        // Safe: every block passed the g_done1 barrier and read g_elr before
        // incrementing g_done2 (program order + fence).
        __threadfence();
        unsigned p2 = atomicAdd(&g_done2, 1u);
        if (p2 == (unsigned)(gridDim.x - 1)) {
            g_elr = 0.0f;
            g_done1 = 0u;
            g_done2 = 0u;
        }
    }
}

extern "C" void kernel_launch(void* const* d_in, const int* in_sizes, int n_in,
                              void* d_out, int out_size) {
    const int*   times  = (const int*)d_in[0];
    const int*   events = (const int*)d_in[1];
    const float* lr     = (const float*)d_in[2];
    float*       out    = (float*)d_out;
    int n = in_sizes[0];

    k_accum<<<1184, 256>>>(times, events, lr, n);

    // PDL launch: k_post prelaunches while k_accum drains.
    cudaLaunchConfig_t cfg = {};
    cfg.gridDim  = {POST_BLOCKS, 1, 1};
    cfg.blockDim = {POST_THREADS, 1, 1};
    cfg.dynamicSmemBytes = 0;
    cfg.stream = 0;
    cudaLaunchAttribute attrs[1];
    attrs[0].id = cudaLaunchAttributeProgrammaticStreamSerialization;
    attrs[0].val.programmaticStreamSerializationAllowed = 1;
    cfg.attrs = attrs;
    cfg.numAttrs = 1;
    cudaLaunchKernelEx(&cfg, k_post, out, out_size);
}

// round 16
// speedup vs baseline: 1.0513x; 1.0513x over previous
#include <cuda_runtime.h>

// EfronLossPenalty — bucketized Efron Cox loss, times in [0, 8192).
// Only per-bucket (d, ers, rss) matter; block log-sum via falling factorial
// -> cancellation-free float Stirling difference.
//
// k_accum: byte-identical to R13 best (branch-free 32-bit RED, PDL trigger).
// k_post:  64 blocks x 128 threads, 1 bucket/thread (proven geometry sweet
//          spot: 16blk=22us, 64blk=11-12us, 128blk=12.7us), ONE cross-block
//          barrier publishing float2{risk,d}; nev derived from chunks; block
//          contributions atomicAdd'ed straight into out (block 0 zeroes out
//          in the PDL preamble, fenced before its barrier arrival).

#define NBINS 8192
#define NREP  16
#define BANK  (NREP * NBINS)
#define FIX_NE 65536.0f
#define FIX_EV 1024.0f
#define POST_BLOCKS 64
#define POST_THREADS 128

// Static scratch — zero at module load; every launch restores the all-zero
// invariant before exiting (graph-replay safe).
__device__ unsigned g_C[2 * BANK];
__device__ float2 g_chunk2[POST_BLOCKS];   // {risk_sum, d_sum} per block
__device__ float g_elr;
__device__ unsigned g_done1;
__device__ unsigned g_done2;

__device__ __forceinline__ float block_reduce_sum(float v) {
    __shared__ float s[32];
    int lane = threadIdx.x & 31;
    int wid  = threadIdx.x >> 5;
    #pragma unroll
    for (int o = 16; o > 0; o >>= 1) v += __shfl_down_sync(0xffffffffu, v, o);
    if (lane == 0) s[wid] = v;
    __syncthreads();
    int nw = (blockDim.x + 31) >> 5;
    v = (threadIdx.x < nw) ? s[threadIdx.x] : 0.0f;
    if (wid == 0) {
        #pragma unroll
        for (int o = 16; o > 0; o >>= 1) v += __shfl_down_sync(0xffffffffu, v, o);
    }
    __syncthreads();   // protect s[] against reuse
    return v;          // valid in thread 0
}

__device__ __forceinline__ void accum_one(int t, int e, float x, unsigned repbase, float& elr) {
    float w = __expf(x);
    float scale = e ? FIX_EV : FIX_NE;            // FSEL
    unsigned wi = (unsigned)fmaf(w, scale, 0.5f); // one FFMA + one F2I
    unsigned val = wi + ((unsigned)e << 24);      // count tag (0 for non-events)
    unsigned idx = repbase + (unsigned)t + (unsigned)e * (unsigned)BANK;
    atomicAdd(&g_C[idx], val);                    // no return use -> REDG.32
    elr += e ? x : 0.0f;
}

__global__ void __launch_bounds__(256) k_accum(
        const int* __restrict__ times, const int* __restrict__ events,
        const float* __restrict__ lr, int n) {
    int tid = blockIdx.x * blockDim.x + threadIdx.x;
    int stride = gridDim.x * blockDim.x;
    unsigned repbase = (((unsigned)(tid >> 5)) & (NREP - 1)) * NBINS;

    const int4*   t4 = (const int4*)times;
    const int4*   e4 = (const int4*)events;
    const float4* l4 = (const float4*)lr;
    int n4 = n >> 2;

    float elr = 0.0f;
    int i = tid;
    // 8 elements per iteration: two int4/float4 triplets in flight (deeper MLP)
    for (; i + stride < n4; i += 2 * stride) {
        int4   ta = t4[i],          tb = t4[i + stride];
        int4   ea = e4[i],          eb = e4[i + stride];
        float4 la = l4[i],          lb = l4[i + stride];
        accum_one(ta.x, ea.x, la.x, repbase, elr);
        accum_one(ta.y, ea.y, la.y, repbase, elr);
        accum_one(ta.z, ea.z, la.z, repbase, elr);
        accum_one(ta.w, ea.w, la.w, repbase, elr);
        accum_one(tb.x, eb.x, lb.x, repbase, elr);
        accum_one(tb.y, eb.y, lb.y, repbase, elr);
        accum_one(tb.z, eb.z, lb.z, repbase, elr);
        accum_one(tb.w, eb.w, lb.w, repbase, elr);
    }
    for (; i < n4; i += stride) {
        int4   tv = t4[i];
        int4   ev = e4[i];
        float4 lv = l4[i];
        accum_one(tv.x, ev.x, lv.x, repbase, elr);
        accum_one(tv.y, ev.y, lv.y, repbase, elr);
        accum_one(tv.z, ev.z, lv.z, repbase, elr);
        accum_one(tv.w, ev.w, lv.w, repbase, elr);
    }
    int base = n4 << 2;
    int rem  = n - base;
    if (tid < rem) accum_one(times[base + tid], events[base + tid], lr[base + tid], repbase, elr);

    float bsum = block_reduce_sum(elr);
    if (threadIdx.x == 0 && bsum != 0.0f) atomicAdd(&g_elr, bsum);

    // PDL: allow dependent k_post grid to launch while remaining blocks drain.
    cudaTriggerProgrammaticLaunchCompletion();
}

// Post-pass: replica reduce (+ re-zero), ONE cross-block barrier publishing
// {risk, d} chunks, per-bucket Efron terms, direct atomicAdd into out.
// 64 blocks x 128 threads, one bucket per thread; all blocks resident.
__global__ void __launch_bounds__(POST_THREADS) k_post(float* __restrict__ out, int out_n) {
    // PDL preamble: block 0 zeroes out (poisoned 0xAA) before the barrier.
    // Each zeroing thread fences so the stores are L2-visible before block 0
    // arrives at the barrier; contributions happen only after the barrier.
    if (blockIdx.x == 0) {
        for (int j = threadIdx.x; j < out_n; j += POST_THREADS) out[j] = 0.0f;
        __threadfence();
    }

    // PDL: wait until ALL accum blocks completed (their writes visible).
    cudaGridDependencySynchronize();

    float elr = 0.0f;
    if (threadIdx.x == 0) elr = g_elr;   // read before any reset can occur

    int b = blockIdx.x * POST_THREADS + threadIdx.x;   // bucket 0..8191

    // --- phase 1: reduce over replicas + banks, restore zeros ---
    unsigned ne_fix = 0u;       // fix16 non-event risk
    unsigned cnt = 0u;          // event count
    unsigned ers_fix = 0u;      // fix10 event risk
    #pragma unroll
    for (int r = 0; r < NREP; r++) {
        int idx = r * NBINS + b;
        unsigned v0 = g_C[idx];          g_C[idx] = 0u;
        unsigned v1 = g_C[idx + BANK];   g_C[idx + BANK] = 0u;
        ne_fix  += v0;
        cnt     += v1 >> 24;
        ers_fix += v1 & 0x00FFFFFFu;
    }
    int   d    = (int)cnt;
    float ers  = (float)ers_fix * (1.0f / FIX_EV);
    float risk = (float)ne_fix * (1.0f / FIX_NE) + ers;

    // --- phase 2: the ONE cross-block barrier ({risk, d} chunk publish) ---
    float crisk = block_reduce_sum(risk);
    float cd    = block_reduce_sum((float)d);
    if (threadIdx.x == 0) {
        g_chunk2[blockIdx.x] = make_float2(crisk, cd);
        __threadfence();
        atomicAdd(&g_done1, 1u);
        while (*((volatile unsigned*)&g_done1) < gridDim.x) { }
    }
    __syncthreads();
    __threadfence();

    float suffix_base = 0.0f;   // risk in blocks above this one
    float nev = 0.0f;           // total events (all chunks)
    #pragma unroll 8
    for (int j = 0; j < POST_BLOCKS; j++) {
        float2 c = g_chunk2[j];
        if (j > blockIdx.x) suffix_base += c.x;
        nev += c.y;
    }
    float inv_nev = 1.0f / fmaxf(nev, 1.0f);

    // intra-block inclusive suffix scan over per-thread risk
    __shared__ float sv[POST_THREADS];
    sv[threadIdx.x] = risk;
    __syncthreads();
    for (int off = 1; off < POST_THREADS; off <<= 1) {
        float add = (threadIdx.x + off < POST_THREADS) ? sv[threadIdx.x + off] : 0.0f;
        __syncthreads();
        sv[threadIdx.x] += add;
        __syncthreads();
    }
    float rss = suffix_base + sv[threadIdx.x];   // inclusive suffix sum at bucket b

    // --- phase 3: Efron terms (all-float, cancellation-free) ---
    float term = 0.0f;
    if (d == 1) {
        term = logf(rss + 1e-12f);
    } else if (d > 1) {
        float s  = ers / (float)d;
        float x  = rss / s;
        float a  = x + 1.0f;
        float bb = x - (float)d + 1.0f;
        if (bb > 0.5f) {
            // F(z) = (z-1/2)ln z - z + 1/(12z); F(a)-F(b) without cancellation:
            float la = logf(a), lb = logf(bb);
            float L  = 0.5f * (la + lb);
            float m  = 0.5f * (a + bb);
            float dlt = log1pf((float)d / bb);
            term = (float)d * (logf(s) + L - 1.0f)
                 + (m - 0.5f) * dlt
                 + (1.0f / 12.0f) * (1.0f / a - 1.0f / bb);
        } else {   // near-clamp fallback (matches reference per-term max(.,eps))
            float sum = 0.0f;
            for (int l = 0; l < d; l++)
                sum += __logf(fmaxf(rss - (float)l * s, 1e-12f));
            term = sum;
        }
    }

    // --- phase 4: direct contribution to out; no second barrier ---
    float tsum = block_reduce_sum(term);
    if (threadIdx.x == 0) {
        float contrib = tsum * inv_nev;
        if (blockIdx.x == 0) contrib -= elr * inv_nev;
        if (contrib != 0.0f) {
            for (int j = 0; j < out_n; j++) atomicAdd(&out[j], contrib);
        }
        // bookkeeping reset: last finisher restores the all-zero invariant.
        // Safe: incrementing g_done2 requires having passed the g_done1
        // barrier and finished all chunk reads (program order + fences).
        __threadfence();
        unsigned p2 = atomicAdd(&g_done2, 1u);
        if (p2 == (unsigned)(gridDim.x - 1)) {
            g_elr = 0.0f;
            g_done1 = 0u;
            g_done2 = 0u;
        }
    }
}

extern "C" void kernel_launch(void* const* d_in, const int* in_sizes, int n_in,
                              void* d_out, int out_size) {
    const int*   times  = (const int*)d_in[0];
    const int*   events = (const int*)d_in[1];
    const float* lr     = (const float*)d_in[2];
    float*       out    = (float*)d_out;
    int n = in_sizes[0];

    k_accum<<<1184, 256>>>(times, events, lr, n);

    // PDL launch: k_post prelaunches while k_accum drains.
    cudaLaunchConfig_t cfg = {};
    cfg.gridDim  = {POST_BLOCKS, 1, 1};
    cfg.blockDim = {POST_THREADS, 1, 1};
    cfg.dynamicSmemBytes = 0;
    cfg.stream = 0;
    cudaLaunchAttribute attrs[1];
    attrs[0].id = cudaLaunchAttributeProgrammaticStreamSerialization;
    attrs[0].val.programmaticStreamSerializationAllowed = 1;
    cfg.attrs = attrs;
    cfg.numAttrs = 1;
    cudaLaunchKernelEx(&cfg, k_post, out, out_size);
}